// round 14
// baseline (speedup 1.0000x reference)
#include <cuda_runtime.h>
#include <cuda_fp16.h>
#include <math.h>
#include <stdint.h>

typedef __half fp16;

#define BATCH 8192
#define PDIM  512
#define H1DIM 1024
#define H2DIM 512
#define NOUTD 1024
#define MMDIM 512
#define NCODE 2048
#define KSTEPS 16

// ---------------- device scratch (no allocations allowed) -------------------
__device__ float g_aA[(size_t)BATCH * NCODE];   // alpha odd  (fp32 state)
__device__ float g_aB[(size_t)BATCH * NCODE];   // alpha even (fp32 state)
#define NCNT (256 + 2 * KSTEPS * 64)            // M1,M2,M3,Z strips + R/A per step
__device__ int   g_cnt[NCNT];

__device__ fp16 g_xs[(size_t)BATCH*PDIM];
__device__ fp16 g_h1[(size_t)BATCH*H1DIM];
__device__ fp16 g_h2[(size_t)BATCH*H2DIM];
__device__ fp16 g_yb[(size_t)BATCH*NOUTD];
__device__ fp16 g_zh[(size_t)BATCH*MMDIM];   // z fp16
__device__ fp16 g_vs[(size_t)BATCH*NCODE];   // v fp16 (GEMM input)
__device__ fp16 g_rs[(size_t)BATCH*MMDIM];   // r
__device__ fp16 g_ap[(size_t)BATCH*NCODE];   // final alpha fp16

__device__ fp16 g_w1[(size_t)H1DIM*PDIM];    // W1^T
__device__ fp16 g_w2[(size_t)H2DIM*H1DIM];   // W2^T
__device__ fp16 g_w3[(size_t)NOUTD*H2DIM];   // W3^T
__device__ fp16 g_m [(size_t)MMDIM*NOUTD];   // M
__device__ fp16 g_aa[(size_t)MMDIM*NCODE];   // A
__device__ fp16 g_at[(size_t)NCODE*MMDIM];   // A^T
__device__ fp16 g_ps[(size_t)NOUTD*NCODE];   // Psi

// ---------------- PTX helpers -------------------------------------------------
__device__ __forceinline__ uint32_t smem_u32(const void* p) {
    uint32_t a;
    asm("{ .reg .u64 t; cvta.to.shared.u64 t, %1; cvt.u32.u64 %0, t; }" : "=r"(a) : "l"(p));
    return a;
}
__device__ __forceinline__ void cp16(uint32_t d, const void* s) {
    asm volatile("cp.async.cg.shared.global [%0], [%1], 16;" :: "r"(d), "l"(s) : "memory");
}
#define CP_COMMIT() asm volatile("cp.async.commit_group;" ::: "memory")
#define CP_WAIT0()  asm volatile("cp.async.wait_group 0;" ::: "memory")

#define LDSM4(r0, r1, r2, r3, a) \
    asm volatile("ldmatrix.sync.aligned.m8n8.x4.shared.b16 {%0,%1,%2,%3}, [%4];" \
                 : "=r"(r0), "=r"(r1), "=r"(r2), "=r"(r3) : "r"(a))

#define MMA16816(c, a, b) \
    asm volatile("mma.sync.aligned.m16n8k16.row.col.f32.f16.f16.f32 " \
                 "{%0,%1,%2,%3}, {%4,%5,%6,%7}, {%8,%9}, {%0,%1,%2,%3};" \
                 : "+f"((c)[0]), "+f"((c)[1]), "+f"((c)[2]), "+f"((c)[3]) \
                 : "r"((a)[0]), "r"((a)[1]), "r"((a)[2]), "r"((a)[3]), \
                   "r"((b)[0]), "r"((b)[1]))

// CTA dependency wait/signal; every wait targets strictly-lower bids
// (monotone dispatch; validated R12/R13 across 71 waves at occ-2).
__device__ __forceinline__ void ctawait(const int* p, int tgt) {
    if (threadIdx.x == 0) {
        const volatile int* vp = (const volatile int*)p;
        while (*vp < tgt) __nanosleep(64);
        __threadfence();
    }
    __syncthreads();
}
__device__ __forceinline__ void ctasignal(int* p) {
    __syncthreads();
    if (threadIdx.x == 0) {
        __threadfence();
        atomicAdd(p, 1);
    }
}

// ---------------- GEMM constants ---------------------------------------------
#define ROW_B   144
#define TILE_B  (128 * ROW_B)            // 18432 B
#define STAGE_B (2 * TILE_B)             // 36864 B
#define SMEM_BYTES (2 * STAGE_B)         // 73728 B -> 2 CTAs/SM

__device__ __forceinline__ float gelu_exact(float x) {
    return 0.5f * x * (1.0f + erff(x * 0.70710678118654752440f));
}
__device__ __forceinline__ void store2h(fp16* H, size_t idx, float o0, float o1) {
    *(__half2*)(H + idx) = __halves2half2(__float2half_rn(o0), __float2half_rn(o1));
}
__device__ __forceinline__ float softf(float u, float thr) {
    return copysignf(fmaxf(fabsf(u) - thr, 0.0f), u);
}
__device__ __forceinline__ float beta_of(int j) {   // reference fp32 recurrence
    float t = 1.0f, b = 0.0f;
    for (int i = 1; i <= j; i++) {
        float tn = 0.5f * (1.0f + sqrtf(1.0f + 4.0f * t * t));
        b = (t - 1.0f) / tn;
        t = tn;
    }
    return b;
}

// ---- shared GEMM mainloop (A[M,K] * B[N,K]^T, fp16, fp32 acc) ----------------
#define GEMM_MAINLOOP(Ag, Bg, Kdim)                                            \
    const fp16* gp[8];                                                          \
    uint32_t so[8];                                                             \
    {                                                                           \
        const fp16* srcs[2] = { (Ag), (Bg) };                                   \
        _Pragma("unroll")                                                       \
        for (int it = 0; it < 8; it++) {                                        \
            const int op  = it >> 2;                                            \
            const int row = (it & 3) * 32 + (tid >> 3);                         \
            const int seg = tid & 7;                                            \
            const int rb  = (op == 0) ? m0 : n0;                                \
            gp[it] = srcs[op] + (size_t)(rb + row) * (Kdim) + seg * 8;          \
            so[it] = (uint32_t)(op * TILE_B + row * ROW_B + seg * 16);          \
        }                                                                       \
    }                                                                           \
    _Pragma("unroll")                                                           \
    for (int it = 0; it < 8; it++) cp16(sbase + so[it], gp[it]);                \
    CP_COMMIT();                                                                \
    const int S = (Kdim) >> 6;                                                  \
    for (int s = 0; s < S; s++) {                                               \
        CP_WAIT0();                                                             \
        __syncthreads();                                                        \
        if (s + 1 < S) {                                                        \
            const uint32_t db = sbase + (uint32_t)(((s + 1) & 1) * STAGE_B);    \
            const int k0 = (s + 1) * 64;                                        \
            _Pragma("unroll")                                                   \
            for (int it = 0; it < 8; it++) cp16(db + so[it], gp[it] + k0);      \
            CP_COMMIT();                                                        \
        }                                                                       \
        const uint32_t st = sbase + (uint32_t)((s & 1) * STAGE_B);              \
        _Pragma("unroll")                                                       \
        for (int kk = 0; kk < 4; kk++) {                                        \
            uint32_t ah[4][4], bh[4][2];                                        \
            _Pragma("unroll")                                                   \
            for (int i = 0; i < 4; i++)                                         \
                LDSM4(ah[i][0], ah[i][1], ah[i][2], ah[i][3],                   \
                      st + aOff + i * (16 * ROW_B) + kk * 32);                  \
            _Pragma("unroll")                                                   \
            for (int j = 0; j < 2; j++) {                                       \
                uint32_t r0, r1, r2, r3;                                        \
                LDSM4(r0, r1, r2, r3,                                           \
                      st + TILE_B + bOff + j * (16 * ROW_B) + kk * 32);         \
                bh[2 * j][0] = r0; bh[2 * j][1] = r1;                           \
                bh[2 * j + 1][0] = r2; bh[2 * j + 1][1] = r3;                   \
            }                                                                   \
            _Pragma("unroll")                                                   \
            for (int i = 0; i < 4; i++)                                         \
                _Pragma("unroll")                                               \
                for (int j = 0; j < 4; j++)                                     \
                    MMA16816(acc[i][j], ah[i], bh[j]);                          \
        }                                                                       \
    }

#define EPI_LOOP_BEGIN(NDIM)                                                   \
    _Pragma("unroll")                                                           \
    for (int i = 0; i < 4; i++)                                                 \
        _Pragma("unroll")                                                       \
        for (int j = 0; j < 4; j++)                                             \
            _Pragma("unroll")                                                   \
            for (int half = 0; half < 2; half++) {                              \
                const int row = m0 + m_w + i * 16 + (lid >> 2) + half * 8;      \
                const int col = n0 + n_w + j * 8 + (lid & 3) * 2;               \
                const size_t idx = (size_t)row * (NDIM) + col;                  \
                float o0 = acc[i][j][half * 2];                                 \
                float o1 = acc[i][j][half * 2 + 1];
#define EPI_LOOP_END }

// ---------------------------------------------------------------------------
// mega: EVERYTHING after prep in one launch.
//   [0,512)      MLP1 (gelu)        [512,768)   MLP2 (gelu)
//   [768,1280)   MLP3 (ybg)         [1280,1536) Z (zsub)
//   [1536, 1536+16*1280)  FISTA steps (256 r + 1024 alpha each)
//   last 512     yhat
// ---------------------------------------------------------------------------
#define B_MLP2 512
#define B_MLP3 768
#define B_Z    1280
#define B_FIST 1536
#define B_YHAT (B_FIST + KSTEPS * 1280)
#define B_TOT  (B_YHAT + 512)

__global__ void __launch_bounds__(256, 2)
mega(const fp16* __restrict__ xs,  const fp16* __restrict__ w1,
     const fp16* __restrict__ w2,  const fp16* __restrict__ w3,
     const fp16* __restrict__ mw,  const fp16* __restrict__ Baa,
     const fp16* __restrict__ Bat, const fp16* __restrict__ Bps,
     fp16* __restrict__ h1b, fp16* __restrict__ h2b, fp16* __restrict__ ybb,
     fp16* __restrict__ zh,  fp16* __restrict__ rsb, fp16* __restrict__ vsb,
     fp16* __restrict__ apo,
     float* __restrict__ aAb, float* __restrict__ aBb,
     float* __restrict__ oybg, float* __restrict__ oz,
     float* __restrict__ oalpha, float* __restrict__ oyhat,
     const float* __restrict__ b1, const float* __restrict__ b2,
     const float* __restrict__ b3, const float* __restrict__ bvec,
     const float* __restrict__ leta, const float* __restrict__ ltau,
     int* __restrict__ cnt)
{
    extern __shared__ char dyn[];
    const uint32_t sbase = smem_u32(dyn);
    const int bid = blockIdx.x;
    const int tid = threadIdx.x;
    const int wid = tid >> 5;
    const int lid = tid & 31;

    int* cntR = cnt + 256;
    int* cntA = cnt + 256 + KSTEPS * 64;

    // ---- decode -----------------------------------------------------------------
    // typ: 0 r, 1 alpha, 2 yhat, 3 gelu, 4 ybg, 5 zsub
    int typ, k = 0, mt, nt, Ndim, Kdim;
    const fp16 *Ag, *Bg;
    const float* auxF = nullptr;   // bias (col) or bvec (row)
    fp16* Chp = nullptr;
    const int* wp = nullptr; int wt = 0;
    int* sp = nullptr;

    if (bid < B_MLP2) {                         // MLP1
        typ = 3; mt = bid >> 3; nt = bid & 7;
        Ndim = H1DIM; Kdim = PDIM; Ag = xs; Bg = w1;
        auxF = b1; Chp = h1b; sp = &cnt[mt];
    } else if (bid < B_MLP3) {                  // MLP2
        int u = bid - B_MLP2; typ = 3; mt = u >> 2; nt = u & 3;
        Ndim = H2DIM; Kdim = H1DIM; Ag = h1b; Bg = w2;
        auxF = b2; Chp = h2b;
        wp = &cnt[mt]; wt = 8; sp = &cnt[64 + mt];
    } else if (bid < B_Z) {                     // MLP3 -> ybg
        int u = bid - B_MLP3; typ = 4; mt = u >> 3; nt = u & 7;
        Ndim = NOUTD; Kdim = H2DIM; Ag = h2b; Bg = w3;
        auxF = b3; Chp = ybb;
        wp = &cnt[64 + mt]; wt = 4; sp = &cnt[128 + mt];
    } else if (bid < B_FIST) {                  // z
        int u = bid - B_Z; typ = 5; mt = u >> 2; nt = u & 3;
        Ndim = MMDIM; Kdim = NOUTD; Ag = ybb; Bg = mw;
        auxF = bvec; Chp = zh;
        wp = &cnt[128 + mt]; wt = 8; sp = &cnt[192 + mt];
    } else if (bid < B_YHAT) {                  // FISTA
        int u = bid - B_FIST;
        k = u / 1280;
        int v = u - k * 1280;
        if (v < 256) {
            typ = 0; mt = v >> 2; nt = v & 3;
            Ndim = MMDIM; Kdim = NCODE; Ag = vsb; Bg = Baa;
            if (k == 0) { wp = &cnt[192 + mt]; wt = 4; }
            else        { wp = &cntA[(k - 1) * 64 + mt]; wt = 16; }
            sp = &cntR[k * 64 + mt];
        } else {
            int v2 = v - 256; typ = 1; mt = v2 >> 4; nt = v2 & 15;
            Ndim = NCODE; Kdim = MMDIM; Ag = rsb; Bg = Bat;
            wp = &cntR[k * 64 + mt]; wt = 4;
            sp = &cntA[k * 64 + mt];
        }
    } else {                                    // yhat
        int u = bid - B_YHAT; typ = 2; mt = u >> 3; nt = u & 7;
        Ndim = NOUTD; Kdim = NCODE; Ag = apo; Bg = Bps;
        wp = &cntA[(KSTEPS - 1) * 64 + mt]; wt = 16;
    }
    const int m0 = mt * 128, n0 = nt * 128;

    if (wp) ctawait(wp, wt);

    // ---- step-0 r path: rs = -z (copy) -------------------------------------------
    if (typ == 0 && k == 0) {
        const uint32_t* zs = (const uint32_t*)zh;
        uint32_t* rd = (uint32_t*)rsb;
#pragma unroll
        for (int i = 0; i < 32; i++) {
            int e = tid + i * 256;
            int r = e >> 6, c = e & 63;
            size_t u32i = (size_t)(m0 + r) * (MMDIM / 2) + (n0 >> 1) + c;
            rd[u32i] = zs[u32i] ^ 0x80008000u;
        }
        ctasignal(sp);
        return;
    }

    const int m_w = (wid >> 2) * 64;
    const int n_w = (wid & 3) * 32;
    const int aRow = (lid & 7) + ((lid >> 3) & 1) * 8;
    const int aK   = ((lid >> 4) & 1) * 8;
    const int bRow = (lid & 7) + ((lid >> 4) & 1) * 8;
    const int bK   = ((lid >> 3) & 1) * 8;
    const uint32_t aOff = (uint32_t)((m_w + aRow) * ROW_B + aK * 2);
    const uint32_t bOff = (uint32_t)((n_w + bRow) * ROW_B + bK * 2);

    float acc[4][4][4];
#pragma unroll
    for (int i = 0; i < 4; i++)
#pragma unroll
        for (int j = 0; j < 4; j++)
#pragma unroll
            for (int c = 0; c < 4; c++) acc[i][j][c] = 0.0f;

    GEMM_MAINLOOP(Ag, Bg, Kdim)

    if (typ == 3) {                               // GELU (MLP1 / MLP2)
        EPI_LOOP_BEGIN(Ndim)
            float2 bv = *(const float2*)&auxF[col];
            store2h(Chp, idx, gelu_exact(o0 + bv.x), gelu_exact(o1 + bv.y));
        EPI_LOOP_END
        ctasignal(sp);
    } else if (typ == 4) {                        // YBG
        EPI_LOOP_BEGIN(NOUTD)
            float2 bv = *(const float2*)&auxF[col];
            o0 += bv.x; o1 += bv.y;
            *(float2*)&oybg[idx] = make_float2(o0, o1);
            store2h(Chp, idx, o0, o1);
        EPI_LOOP_END
        ctasignal(sp);
    } else if (typ == 5) {                        // ZSUB
        EPI_LOOP_BEGIN(MMDIM)
            float2 av = *(const float2*)&auxF[idx];
            float z0 = av.x - o0, z1 = av.y - o1;
            *(float2*)&oz[idx] = make_float2(z0, z1);
            store2h(Chp, idx, z0, z1);
        EPI_LOOP_END
        ctasignal(sp);
    } else if (typ == 0) {                        // r = acc - z
        EPI_LOOP_BEGIN(MMDIM)
            __half2 zv = *(const __half2*)&zh[idx];
            store2h(rsb, idx, o0 - __half2float(__low2half(zv)),
                              o1 - __half2float(__high2half(zv)));
        EPI_LOOP_END
        ctasignal(sp);
    } else if (typ == 1) {                        // alpha step
        float eta = expf(leta[k]);  eta = fminf(fmaxf(eta, 1e-8f), 10.0f);
        float tau = expf(ltau[k]); tau = fminf(fmaxf(tau, 1e-8f), 10.0f);
        const float thr = eta * tau;
        if (k == 0) {
            EPI_LOOP_BEGIN(NCODE)
                float a0n = softf(-eta * o0, thr);
                float a1n = softf(-eta * o1, thr);
                *(float2*)&aAb[idx] = make_float2(a0n, a1n);
                store2h(vsb, idx, a0n, a1n);      // v1 = alpha1 (beta1 = 0)
            EPI_LOOP_END
        } else if (k < KSTEPS - 1) {
            const float betaV = beta_of(k);
            const float betaN = beta_of(k + 1);
            const float* acur  = (k & 1) ? aAb : aBb;
            const float* aprev = (k == 1) ? acur : ((k & 1) ? aBb : aAb);
            float* adst = (k & 1) ? aBb : aAb;
            EPI_LOOP_BEGIN(NCODE)
                float2 ac = *(const float2*)&acur[idx];
                float2 ap = *(const float2*)&aprev[idx];
                float v0 = ac.x + betaV * (ac.x - ap.x);
                float v1 = ac.y + betaV * (ac.y - ap.y);
                float a0n = softf(v0 - eta * o0, thr);
                float a1n = softf(v1 - eta * o1, thr);
                float vn0 = a0n + betaN * (a0n - ac.x);
                float vn1 = a1n + betaN * (a1n - ac.y);
                *(float2*)&adst[idx] = make_float2(a0n, a1n);
                store2h(vsb, idx, vn0, vn1);
            EPI_LOOP_END
        } else {
            const float betaV = beta_of(KSTEPS - 1);
            EPI_LOOP_BEGIN(NCODE)
                float2 ac = *(const float2*)&aAb[idx];   // alpha_15 (odd)
                float2 ap = *(const float2*)&aBb[idx];   // alpha_14
                float v0 = ac.x + betaV * (ac.x - ap.x);
                float v1 = ac.y + betaV * (ac.y - ap.y);
                float a0n = softf(v0 - eta * o0, thr);
                float a1n = softf(v1 - eta * o1, thr);
                *(float2*)&oalpha[idx] = make_float2(a0n, a1n);
                store2h(apo, idx, a0n, a1n);
            EPI_LOOP_END
        }
        ctasignal(sp);
    } else {                                      // yhat
        EPI_LOOP_BEGIN(NOUTD)
            float2 yv = *(const float2*)&oybg[idx];
            *(float2*)&oyhat[idx] = make_float2(o0 + yv.x, o1 + yv.y);
        EPI_LOOP_END
    }
}

// ---------------------------------------------------------------------------
// prep: all fp32->fp16 rounds + counter zeroing in ONE kernel
// ---------------------------------------------------------------------------
__global__ void round_all(const float4* __restrict__ x, const float4* __restrict__ A,
                          const float4* __restrict__ Mm, const float4* __restrict__ Ps,
                          fp16* __restrict__ xs, fp16* __restrict__ aa,
                          fp16* __restrict__ mw, fp16* __restrict__ ps,
                          int* __restrict__ cnt)
{
    int b = blockIdx.x;
    const float4* s; fp16* o; int b0;
    if      (b < 4096) { s = x;  o = xs; b0 = b; }          // 8192*512/1024
    else if (b < 5120) { s = A;  o = aa; b0 = b - 4096; }   // 512*2048/1024
    else if (b < 5632) { s = Mm; o = mw; b0 = b - 5120; }   // 512*1024/1024
    else if (b < 7680) { s = Ps; o = ps; b0 = b - 5632; }   // 1024*2048/1024
    else {                                                   // zero counters
        int i = (b - 7680) * 256 + threadIdx.x;
        if (i < NCNT) cnt[i] = 0;
        return;
    }
    int i = b0 * 256 + threadIdx.x;
    float4 v = s[i];
    size_t idx = (size_t)i * 4;
    *(__half2*)(o + idx)     = __halves2half2(__float2half_rn(v.x), __float2half_rn(v.y));
    *(__half2*)(o + idx + 2) = __halves2half2(__float2half_rn(v.z), __float2half_rn(v.w));
}

// all transposing rounds in ONE kernel (threads (32,8))
__global__ void tround_all(const float* __restrict__ W1, const float* __restrict__ W2,
                           const float* __restrict__ W3, const float* __restrict__ A,
                           fp16* __restrict__ w1, fp16* __restrict__ w2,
                           fp16* __restrict__ w3, fp16* __restrict__ at)
{
    int b = blockIdx.x;
    const float* s; fp16* o; int R, C, bx, by;
    if      (b < 512)  { s = W1; o = w1; R = PDIM;  C = H1DIM; bx = (b & 31) * 32; by = (b >> 5) * 32; }
    else if (b < 1024) { int t = b - 512;  s = W2; o = w2; R = H1DIM; C = H2DIM; bx = (t & 15) * 32; by = (t >> 4) * 32; }
    else if (b < 1536) { int t = b - 1024; s = W3; o = w3; R = H2DIM; C = NOUTD; bx = (t & 31) * 32; by = (t >> 5) * 32; }
    else               { int t = b - 1536; s = A;  o = at; R = MMDIM; C = NCODE; bx = (t & 63) * 32; by = (t >> 6) * 32; }

    __shared__ float t[32][33];
    const int x = threadIdx.x, y = threadIdx.y;
#pragma unroll
    for (int i = 0; i < 4; i++)
        t[y + i * 8][x] = s[(size_t)(by + y + i * 8) * C + bx + x];
    __syncthreads();
#pragma unroll
    for (int i = 0; i < 4; i++)
        o[(size_t)(bx + y + i * 8) * R + by + x] = __float2half_rn(t[x][y + i * 8]);
}

// ---------------------------------------------------------------------------
extern "C" void kernel_launch(void* const* d_in, const int* in_sizes, int n_in,
                              void* d_out, int out_size)
{
    const float* x    = (const float*)d_in[0];
    const float* bvec = (const float*)d_in[1];
    const float* W1   = (const float*)d_in[2];
    const float* b1   = (const float*)d_in[3];
    const float* W2   = (const float*)d_in[4];
    const float* b2   = (const float*)d_in[5];
    const float* W3   = (const float*)d_in[6];
    const float* b3   = (const float*)d_in[7];
    const float* A    = (const float*)d_in[8];
    const float* leta = (const float*)d_in[9];
    const float* ltau = (const float*)d_in[10];
    const float* Psi  = (const float*)d_in[11];
    const float* Mmat = (const float*)d_in[12];

    float* out     = (float*)d_out;
    float* o_ybg   = out;
    float* o_z     = o_ybg   + (size_t)BATCH * NOUTD;
    float* o_alpha = o_z     + (size_t)BATCH * MMDIM;
    float* o_yhat  = o_alpha + (size_t)BATCH * NCODE;

#define SYM(p, s) void* p##_; cudaGetSymbolAddress(&p##_, s); auto* p = (decltype(&s[0]))p##_
    SYM(aA, g_aA);   SYM(aB, g_aB);   SYM(cnt, g_cnt);
    SYM(xs, g_xs);   SYM(h1, g_h1);   SYM(h2, g_h2);   SYM(yb, g_yb);
    SYM(zh, g_zh);   SYM(vs, g_vs);   SYM(rs, g_rs);   SYM(ap, g_ap);
    SYM(w1, g_w1);   SYM(w2, g_w2);   SYM(w3, g_w3);
    SYM(mw, g_m);    SYM(aa, g_aa);   SYM(at, g_at);   SYM(ps, g_ps);
#undef SYM

    cudaFuncSetAttribute((void*)mega, cudaFuncAttributeMaxDynamicSharedMemorySize, SMEM_BYTES);

    // ---- prep: 2 launches --------------------------------------------------------
    round_all<<<7680 + (NCNT + 255) / 256, 256>>>(
        (const float4*)x, (const float4*)A, (const float4*)Mmat, (const float4*)Psi,
        xs, aa, mw, ps, cnt);
    tround_all<<<2560, dim3(32, 8)>>>(W1, W2, W3, A, w1, w2, w3, at);

    // ---- everything else: 1 launch -------------------------------------------------
    mega<<<B_TOT, 256, SMEM_BYTES>>>(
        xs, w1, w2, w3, mw, aa, at, ps,
        h1, h2, yb, zh, rs, vs, ap,
        aA, aB, o_ybg, o_z, o_alpha, o_yhat,
        b1, b2, b3, bvec, leta, ltau, cnt);
}

// round 15
// speedup vs baseline: 1.0252x; 1.0252x over previous
#include <cuda_runtime.h>
#include <cuda_fp16.h>
#include <math.h>
#include <stdint.h>

typedef __half fp16;

#define BATCH 8192
#define PDIM  512
#define H1DIM 1024
#define H2DIM 512
#define NOUTD 1024
#define MMDIM 512
#define NCODE 2048
#define KSTEPS 16

// ---------------- device scratch (no allocations allowed) -------------------
__device__ float g_aA[(size_t)BATCH * NCODE];   // alpha odd  (fp32 state)
__device__ float g_aB[(size_t)BATCH * NCODE];   // alpha even (fp32 state)
#define NCNT (2 * KSTEPS * 64)
__device__ int   g_cnt[NCNT];                   // cntR | cntA

__device__ fp16 g_xs[(size_t)BATCH*PDIM];
__device__ fp16 g_h1[(size_t)BATCH*H1DIM];
__device__ fp16 g_h2[(size_t)BATCH*H2DIM];
__device__ fp16 g_yb[(size_t)BATCH*NOUTD];
__device__ fp16 g_zh[(size_t)BATCH*MMDIM];   // z fp16
__device__ fp16 g_vs[(size_t)BATCH*NCODE];   // v fp16 (GEMM input)
__device__ fp16 g_rs[(size_t)BATCH*MMDIM];   // r
__device__ fp16 g_ap[(size_t)BATCH*NCODE];   // final alpha fp16

__device__ fp16 g_w1[(size_t)H1DIM*PDIM];    // W1^T
__device__ fp16 g_w2[(size_t)H2DIM*H1DIM];   // W2^T
__device__ fp16 g_w3[(size_t)NOUTD*H2DIM];   // W3^T
__device__ fp16 g_m [(size_t)MMDIM*NOUTD];   // M
__device__ fp16 g_aa[(size_t)MMDIM*NCODE];   // A
__device__ fp16 g_at[(size_t)NCODE*MMDIM];   // A^T
__device__ fp16 g_ps[(size_t)NOUTD*NCODE];   // Psi

// ---------------- PTX helpers -------------------------------------------------
__device__ __forceinline__ uint32_t smem_u32(const void* p) {
    uint32_t a;
    asm("{ .reg .u64 t; cvta.to.shared.u64 t, %1; cvt.u32.u64 %0, t; }" : "=r"(a) : "l"(p));
    return a;
}
__device__ __forceinline__ void cp16(uint32_t d, const void* s) {
    asm volatile("cp.async.cg.shared.global [%0], [%1], 16;" :: "r"(d), "l"(s) : "memory");
}
#define CP_COMMIT() asm volatile("cp.async.commit_group;" ::: "memory")
#define CP_WAIT0()  asm volatile("cp.async.wait_group 0;" ::: "memory")

#define LDSM4(r0, r1, r2, r3, a) \
    asm volatile("ldmatrix.sync.aligned.m8n8.x4.shared.b16 {%0,%1,%2,%3}, [%4];" \
                 : "=r"(r0), "=r"(r1), "=r"(r2), "=r"(r3) : "r"(a))

#define MMA16816(c, a, b) \
    asm volatile("mma.sync.aligned.m16n8k16.row.col.f32.f16.f16.f32 " \
                 "{%0,%1,%2,%3}, {%4,%5,%6,%7}, {%8,%9}, {%0,%1,%2,%3};" \
                 : "+f"((c)[0]), "+f"((c)[1]), "+f"((c)[2]), "+f"((c)[3]) \
                 : "r"((a)[0]), "r"((a)[1]), "r"((a)[2]), "r"((a)[3]), \
                   "r"((b)[0]), "r"((b)[1]))

// CTA dependency wait/signal; every wait targets strictly-lower bids
// (monotone dispatch; validated R12/R13 across 71 waves at occ-2).
__device__ __forceinline__ void ctawait(const int* p, int tgt) {
    if (threadIdx.x == 0) {
        const volatile int* vp = (const volatile int*)p;
        while (*vp < tgt) __nanosleep(64);
        __threadfence();
    }
    __syncthreads();
}
__device__ __forceinline__ void ctasignal(int* p) {
    __syncthreads();
    if (threadIdx.x == 0) {
        __threadfence();
        atomicAdd(p, 1);
    }
}

// ---------------- GEMM constants ---------------------------------------------
#define ROW_B   144
#define TILE_B  (128 * ROW_B)            // 18432 B
#define STAGE_B (2 * TILE_B)             // 36864 B
#define SMEM_BYTES (2 * STAGE_B)         // 73728 B -> 2 CTAs/SM

enum { EPI_GELU = 0, EPI_YBG, EPI_ZSUB };

__device__ __forceinline__ float gelu_exact(float x) {
    return 0.5f * x * (1.0f + erff(x * 0.70710678118654752440f));
}
__device__ __forceinline__ void store2h(fp16* H, size_t idx, float o0, float o1) {
    *(__half2*)(H + idx) = __halves2half2(__float2half_rn(o0), __float2half_rn(o1));
}
__device__ __forceinline__ float softf(float u, float thr) {
    return copysignf(fmaxf(fabsf(u) - thr, 0.0f), u);
}
__device__ __forceinline__ float beta_of(int j) {   // reference fp32 recurrence
    float t = 1.0f, b = 0.0f;
    for (int i = 1; i <= j; i++) {
        float tn = 0.5f * (1.0f + sqrtf(1.0f + 4.0f * t * t));
        b = (t - 1.0f) / tn;
        t = tn;
    }
    return b;
}

// ---- shared GEMM mainloop (A[M,K] * B[N,K]^T, fp16, fp32 acc) ----------------
#define GEMM_MAINLOOP(Ag, Bg, Kdim)                                            \
    const fp16* gp[8];                                                          \
    uint32_t so[8];                                                             \
    {                                                                           \
        const fp16* srcs[2] = { (Ag), (Bg) };                                   \
        _Pragma("unroll")                                                       \
        for (int it = 0; it < 8; it++) {                                        \
            const int op  = it >> 2;                                            \
            const int row = (it & 3) * 32 + (tid >> 3);                         \
            const int seg = tid & 7;                                            \
            const int rb  = (op == 0) ? m0 : n0;                                \
            gp[it] = srcs[op] + (size_t)(rb + row) * (Kdim) + seg * 8;          \
            so[it] = (uint32_t)(op * TILE_B + row * ROW_B + seg * 16);          \
        }                                                                       \
    }                                                                           \
    _Pragma("unroll")                                                           \
    for (int it = 0; it < 8; it++) cp16(sbase + so[it], gp[it]);                \
    CP_COMMIT();                                                                \
    const int S = (Kdim) >> 6;                                                  \
    for (int s = 0; s < S; s++) {                                               \
        CP_WAIT0();                                                             \
        __syncthreads();                                                        \
        if (s + 1 < S) {                                                        \
            const uint32_t db = sbase + (uint32_t)(((s + 1) & 1) * STAGE_B);    \
            const int k0 = (s + 1) * 64;                                        \
            _Pragma("unroll")                                                   \
            for (int it = 0; it < 8; it++) cp16(db + so[it], gp[it] + k0);      \
            CP_COMMIT();                                                        \
        }                                                                       \
        const uint32_t st = sbase + (uint32_t)((s & 1) * STAGE_B);              \
        _Pragma("unroll")                                                       \
        for (int kk = 0; kk < 4; kk++) {                                        \
            uint32_t ah[4][4], bh[4][2];                                        \
            _Pragma("unroll")                                                   \
            for (int i = 0; i < 4; i++)                                         \
                LDSM4(ah[i][0], ah[i][1], ah[i][2], ah[i][3],                   \
                      st + aOff + i * (16 * ROW_B) + kk * 32);                  \
            _Pragma("unroll")                                                   \
            for (int j = 0; j < 2; j++) {                                       \
                uint32_t r0, r1, r2, r3;                                        \
                LDSM4(r0, r1, r2, r3,                                           \
                      st + TILE_B + bOff + j * (16 * ROW_B) + kk * 32);         \
                bh[2 * j][0] = r0; bh[2 * j][1] = r1;                           \
                bh[2 * j + 1][0] = r2; bh[2 * j + 1][1] = r3;                   \
            }                                                                   \
            _Pragma("unroll")                                                   \
            for (int i = 0; i < 4; i++)                                         \
                _Pragma("unroll")                                               \
                for (int j = 0; j < 4; j++)                                     \
                    MMA16816(acc[i][j], ah[i], bh[j]);                          \
        }                                                                       \
    }

#define EPI_LOOP_BEGIN(NDIM)                                                   \
    _Pragma("unroll")                                                           \
    for (int i = 0; i < 4; i++)                                                 \
        _Pragma("unroll")                                                       \
        for (int j = 0; j < 4; j++)                                             \
            _Pragma("unroll")                                                   \
            for (int half = 0; half < 2; half++) {                              \
                const int row = m0 + m_w + i * 16 + (lid >> 2) + half * 8;      \
                const int col = n0 + n_w + j * 8 + (lid & 3) * 2;               \
                const size_t idx = (size_t)row * (NDIM) + col;                  \
                float o0 = acc[i][j][half * 2];                                 \
                float o1 = acc[i][j][half * 2 + 1];
#define EPI_LOOP_END }

// ---------------------------------------------------------------------------
// wgemm: standalone GEMM for MLP / z phases (separate launches — R14 showed
// that fusing the short serial MLP chain into one launch regresses).
// ---------------------------------------------------------------------------
template <int EPI>
__global__ void __launch_bounds__(256, 2)
wgemm(const fp16* __restrict__ Ag, const fp16* __restrict__ Bg,
      int Ndim, int Kdim,
      float* __restrict__ C0, fp16* __restrict__ Ch,
      const float* __restrict__ aux)
{
    extern __shared__ char dyn[];
    const uint32_t sbase = smem_u32(dyn);
    const int tid = threadIdx.x;
    const int wid = tid >> 5;
    const int lid = tid & 31;
    const int m0  = blockIdx.y * 128;
    const int n0  = blockIdx.x * 128;
    const int m_w = (wid >> 2) * 64;
    const int n_w = (wid & 3) * 32;

    const int aRow = (lid & 7) + ((lid >> 3) & 1) * 8;
    const int aK   = ((lid >> 4) & 1) * 8;
    const int bRow = (lid & 7) + ((lid >> 4) & 1) * 8;
    const int bK   = ((lid >> 3) & 1) * 8;
    const uint32_t aOff = (uint32_t)((m_w + aRow) * ROW_B + aK * 2);
    const uint32_t bOff = (uint32_t)((n_w + bRow) * ROW_B + bK * 2);

    float acc[4][4][4];
#pragma unroll
    for (int i = 0; i < 4; i++)
#pragma unroll
        for (int j = 0; j < 4; j++)
#pragma unroll
            for (int c = 0; c < 4; c++) acc[i][j][c] = 0.0f;

    GEMM_MAINLOOP(Ag, Bg, Kdim)

    EPI_LOOP_BEGIN(Ndim)
        if (EPI == EPI_GELU) {
            float2 bv = *(const float2*)&aux[col];
            store2h(Ch, idx, gelu_exact(o0 + bv.x), gelu_exact(o1 + bv.y));
        } else if (EPI == EPI_YBG) {
            float2 bv = *(const float2*)&aux[col];
            o0 += bv.x; o1 += bv.y;
            *(float2*)&C0[idx] = make_float2(o0, o1);
            store2h(Ch, idx, o0, o1);
        } else {                                   // EPI_ZSUB
            float2 av = *(const float2*)&aux[idx];
            float z0 = av.x - o0, z1 = av.y - o1;
            *(float2*)&C0[idx] = make_float2(z0, z1);
            store2h(Ch, idx, z0, z1);
        }
    EPI_LOOP_END
}

// ---------------------------------------------------------------------------
// floop: ALL 16 FISTA steps + yhat in ONE launch (validated R13).
// ---------------------------------------------------------------------------
__global__ void __launch_bounds__(256, 2)
floop(const fp16* __restrict__ Baa, const fp16* __restrict__ Bat,
      const fp16* __restrict__ Bps,
      const fp16* __restrict__ zh, fp16* __restrict__ rsb,
      fp16* __restrict__ vsb, fp16* __restrict__ apo,
      float* __restrict__ aAb, float* __restrict__ aBb,
      float* __restrict__ oalpha, float* __restrict__ oyhat,
      const float* __restrict__ oybg,
      const float* __restrict__ leta, const float* __restrict__ ltau,
      int* __restrict__ cnt)
{
    extern __shared__ char dyn[];
    const uint32_t sbase = smem_u32(dyn);
    const int bid = blockIdx.x;
    const int tid = threadIdx.x;
    const int wid = tid >> 5;
    const int lid = tid & 31;

    int* cntR = cnt;
    int* cntA = cnt + KSTEPS * 64;

    int typ;             // 0 = r, 1 = alpha, 2 = yhat
    int k = 0, mt, nt, Ndim, Kdim;
    const fp16 *Ag, *Bg;
    if (bid < KSTEPS * 1280) {
        k = bid / 1280;
        int u = bid - k * 1280;
        if (u < 256) { typ = 0; mt = u >> 2; nt = u & 3;
                       Ndim = MMDIM; Kdim = NCODE; Ag = vsb; Bg = Baa; }
        else { int u2 = u - 256; typ = 1; mt = u2 >> 4; nt = u2 & 15;
               Ndim = NCODE; Kdim = MMDIM; Ag = rsb; Bg = Bat; }
    } else {
        int u = bid - KSTEPS * 1280;
        typ = 2; mt = u >> 3; nt = u & 7;
        Ndim = NOUTD; Kdim = NCODE; Ag = apo; Bg = Bps;
    }
    const int m0 = mt * 128, n0 = nt * 128;

    // step-0 r path: rs = -z (copy)
    if (typ == 0 && k == 0) {
        const uint32_t* zs = (const uint32_t*)zh;
        uint32_t* rd = (uint32_t*)rsb;
#pragma unroll
        for (int i = 0; i < 32; i++) {
            int e = tid + i * 256;
            int r = e >> 6, c = e & 63;
            size_t u32i = (size_t)(m0 + r) * (MMDIM / 2) + (n0 >> 1) + c;
            rd[u32i] = zs[u32i] ^ 0x80008000u;
        }
        ctasignal(&cntR[mt]);
        return;
    }

    if (typ == 0)       ctawait(&cntA[(k - 1) * 64 + mt], 16);
    else if (typ == 1)  ctawait(&cntR[k * 64 + mt], 4);
    else                ctawait(&cntA[(KSTEPS - 1) * 64 + mt], 16);

    const int m_w = (wid >> 2) * 64;
    const int n_w = (wid & 3) * 32;
    const int aRow = (lid & 7) + ((lid >> 3) & 1) * 8;
    const int aK   = ((lid >> 4) & 1) * 8;
    const int bRow = (lid & 7) + ((lid >> 4) & 1) * 8;
    const int bK   = ((lid >> 3) & 1) * 8;
    const uint32_t aOff = (uint32_t)((m_w + aRow) * ROW_B + aK * 2);
    const uint32_t bOff = (uint32_t)((n_w + bRow) * ROW_B + bK * 2);

    float acc[4][4][4];
#pragma unroll
    for (int i = 0; i < 4; i++)
#pragma unroll
        for (int j = 0; j < 4; j++)
#pragma unroll
            for (int c = 0; c < 4; c++) acc[i][j][c] = 0.0f;

    GEMM_MAINLOOP(Ag, Bg, Kdim)

    if (typ == 0) {
        EPI_LOOP_BEGIN(MMDIM)
            __half2 zv = *(const __half2*)&zh[idx];
            store2h(rsb, idx, o0 - __half2float(__low2half(zv)),
                              o1 - __half2float(__high2half(zv)));
        EPI_LOOP_END
        ctasignal(&cntR[k * 64 + mt]);
    } else if (typ == 1) {
        float eta = expf(leta[k]);  eta = fminf(fmaxf(eta, 1e-8f), 10.0f);
        float tau = expf(ltau[k]); tau = fminf(fmaxf(tau, 1e-8f), 10.0f);
        const float thr = eta * tau;
        if (k == 0) {
            EPI_LOOP_BEGIN(NCODE)
                float a0n = softf(-eta * o0, thr);
                float a1n = softf(-eta * o1, thr);
                *(float2*)&aAb[idx] = make_float2(a0n, a1n);
                store2h(vsb, idx, a0n, a1n);       // v1 = alpha1 (beta1 = 0)
            EPI_LOOP_END
        } else if (k < KSTEPS - 1) {
            const float betaV = beta_of(k);
            const float betaN = beta_of(k + 1);
            const float* acur  = (k & 1) ? aAb : aBb;
            const float* aprev = (k == 1) ? acur : ((k & 1) ? aBb : aAb);
            float* adst = (k & 1) ? aBb : aAb;
            EPI_LOOP_BEGIN(NCODE)
                float2 ac = *(const float2*)&acur[idx];
                float2 ap = *(const float2*)&aprev[idx];
                float v0 = ac.x + betaV * (ac.x - ap.x);
                float v1 = ac.y + betaV * (ac.y - ap.y);
                float a0n = softf(v0 - eta * o0, thr);
                float a1n = softf(v1 - eta * o1, thr);
                float vn0 = a0n + betaN * (a0n - ac.x);
                float vn1 = a1n + betaN * (a1n - ac.y);
                *(float2*)&adst[idx] = make_float2(a0n, a1n);
                store2h(vsb, idx, vn0, vn1);
            EPI_LOOP_END
        } else {
            const float betaV = beta_of(KSTEPS - 1);
            EPI_LOOP_BEGIN(NCODE)
                float2 ac = *(const float2*)&aAb[idx];   // alpha_15 (odd)
                float2 ap = *(const float2*)&aBb[idx];   // alpha_14
                float v0 = ac.x + betaV * (ac.x - ap.x);
                float v1 = ac.y + betaV * (ac.y - ap.y);
                float a0n = softf(v0 - eta * o0, thr);
                float a1n = softf(v1 - eta * o1, thr);
                *(float2*)&oalpha[idx] = make_float2(a0n, a1n);
                store2h(apo, idx, a0n, a1n);
            EPI_LOOP_END
        }
        ctasignal(&cntA[k * 64 + mt]);
    } else {
        EPI_LOOP_BEGIN(NOUTD)
            float2 yv = *(const float2*)&oybg[idx];
            *(float2*)&oyhat[idx] = make_float2(o0 + yv.x, o1 + yv.y);
        EPI_LOOP_END
    }
}

// ---------------------------------------------------------------------------
// prep: all fp32->fp16 rounds + counter zeroing in ONE kernel (validated R14)
// ---------------------------------------------------------------------------
__global__ void round_all(const float4* __restrict__ x, const float4* __restrict__ A,
                          const float4* __restrict__ Mm, const float4* __restrict__ Ps,
                          fp16* __restrict__ xs, fp16* __restrict__ aa,
                          fp16* __restrict__ mw, fp16* __restrict__ ps,
                          int* __restrict__ cnt)
{
    int b = blockIdx.x;
    const float4* s; fp16* o; int b0;
    if      (b < 4096) { s = x;  o = xs; b0 = b; }
    else if (b < 5120) { s = A;  o = aa; b0 = b - 4096; }
    else if (b < 5632) { s = Mm; o = mw; b0 = b - 5120; }
    else if (b < 7680) { s = Ps; o = ps; b0 = b - 5632; }
    else {
        int i = (b - 7680) * 256 + threadIdx.x;
        if (i < NCNT) cnt[i] = 0;
        return;
    }
    int i = b0 * 256 + threadIdx.x;
    float4 v = s[i];
    size_t idx = (size_t)i * 4;
    *(__half2*)(o + idx)     = __halves2half2(__float2half_rn(v.x), __float2half_rn(v.y));
    *(__half2*)(o + idx + 2) = __halves2half2(__float2half_rn(v.z), __float2half_rn(v.w));
}

// all transposing rounds in ONE kernel (threads (32,8))
__global__ void tround_all(const float* __restrict__ W1, const float* __restrict__ W2,
                           const float* __restrict__ W3, const float* __restrict__ A,
                           fp16* __restrict__ w1, fp16* __restrict__ w2,
                           fp16* __restrict__ w3, fp16* __restrict__ at)
{
    int b = blockIdx.x;
    const float* s; fp16* o; int R, C, bx, by;
    if      (b < 512)  { s = W1; o = w1; R = PDIM;  C = H1DIM; bx = (b & 31) * 32; by = (b >> 5) * 32; }
    else if (b < 1024) { int u = b - 512;  s = W2; o = w2; R = H1DIM; C = H2DIM; bx = (u & 15) * 32; by = (u >> 4) * 32; }
    else if (b < 1536) { int u = b - 1024; s = W3; o = w3; R = H2DIM; C = NOUTD; bx = (u & 31) * 32; by = (u >> 5) * 32; }
    else               { int u = b - 1536; s = A;  o = at; R = MMDIM; C = NCODE; bx = (u & 63) * 32; by = (u >> 6) * 32; }

    __shared__ float t[32][33];
    const int x = threadIdx.x, y = threadIdx.y;
#pragma unroll
    for (int i = 0; i < 4; i++)
        t[y + i * 8][x] = s[(size_t)(by + y + i * 8) * C + bx + x];
    __syncthreads();
#pragma unroll
    for (int i = 0; i < 4; i++)
        o[(size_t)(bx + y + i * 8) * R + by + x] = __float2half_rn(t[x][y + i * 8]);
}

// ---------------------------------------------------------------------------
extern "C" void kernel_launch(void* const* d_in, const int* in_sizes, int n_in,
                              void* d_out, int out_size)
{
    const float* x    = (const float*)d_in[0];
    const float* bvec = (const float*)d_in[1];
    const float* W1   = (const float*)d_in[2];
    const float* b1   = (const float*)d_in[3];
    const float* W2   = (const float*)d_in[4];
    const float* b2   = (const float*)d_in[5];
    const float* W3   = (const float*)d_in[6];
    const float* b3   = (const float*)d_in[7];
    const float* A    = (const float*)d_in[8];
    const float* leta = (const float*)d_in[9];
    const float* ltau = (const float*)d_in[10];
    const float* Psi  = (const float*)d_in[11];
    const float* Mmat = (const float*)d_in[12];

    float* out     = (float*)d_out;
    float* o_ybg   = out;
    float* o_z     = o_ybg   + (size_t)BATCH * NOUTD;
    float* o_alpha = o_z     + (size_t)BATCH * MMDIM;
    float* o_yhat  = o_alpha + (size_t)BATCH * NCODE;

#define SYM(p, s) void* p##_; cudaGetSymbolAddress(&p##_, s); auto* p = (decltype(&s[0]))p##_
    SYM(aA, g_aA);   SYM(aB, g_aB);   SYM(cnt, g_cnt);
    SYM(xs, g_xs);   SYM(h1, g_h1);   SYM(h2, g_h2);   SYM(yb, g_yb);
    SYM(zh, g_zh);   SYM(vs, g_vs);   SYM(rs, g_rs);   SYM(ap, g_ap);
    SYM(w1, g_w1);   SYM(w2, g_w2);   SYM(w3, g_w3);
    SYM(mw, g_m);    SYM(aa, g_aa);   SYM(at, g_at);   SYM(ps, g_ps);
#undef SYM

    cudaFuncSetAttribute((void*)wgemm<EPI_GELU>, cudaFuncAttributeMaxDynamicSharedMemorySize, SMEM_BYTES);
    cudaFuncSetAttribute((void*)wgemm<EPI_YBG>,  cudaFuncAttributeMaxDynamicSharedMemorySize, SMEM_BYTES);
    cudaFuncSetAttribute((void*)wgemm<EPI_ZSUB>, cudaFuncAttributeMaxDynamicSharedMemorySize, SMEM_BYTES);
    cudaFuncSetAttribute((void*)floop, cudaFuncAttributeMaxDynamicSharedMemorySize, SMEM_BYTES);

    // ---- prep: 2 launches ------------------------------------------------------
    round_all<<<7680 + (NCNT + 255) / 256, 256>>>(
        (const float4*)x, (const float4*)A, (const float4*)Mmat, (const float4*)Psi,
        xs, aa, mw, ps, cnt);
    tround_all<<<2560, dim3(32, 8)>>>(W1, W2, W3, A, w1, w2, w3, at);

    const dim3 blk(256);
#define GRID(N) dim3((N) / 128, BATCH / 128)
#define NUL0 (float*)nullptr
#define NULH (fp16*)nullptr

    // ---- background MLP + z (separate launches; R14 showed fusing regresses) ----
    wgemm<EPI_GELU><<<GRID(H1DIM), blk, SMEM_BYTES>>>(xs, w1, H1DIM, PDIM, NUL0, h1, b1);
    wgemm<EPI_GELU><<<GRID(H2DIM), blk, SMEM_BYTES>>>(h1, w2, H2DIM, H1DIM, NUL0, h2, b2);
    wgemm<EPI_YBG> <<<GRID(NOUTD), blk, SMEM_BYTES>>>(h2, w3, NOUTD, H2DIM, o_ybg, yb, b3);
    wgemm<EPI_ZSUB><<<GRID(MMDIM), blk, SMEM_BYTES>>>(yb, mw, MMDIM, NOUTD, o_z, zh, bvec);

    // ---- all 16 FISTA steps + yhat in ONE launch --------------------------------
    const int FG = KSTEPS * 1280 + 512;   // 20992
    floop<<<FG, blk, SMEM_BYTES>>>(aa, at, ps, zh, rs, vs, ap,
                                   aA, aB, o_alpha, o_yhat, o_ybg,
                                   leta, ltau, cnt);
}